// round 10
// baseline (speedup 1.0000x reference)
#include <cuda_runtime.h>

#define FULLMASK 0xffffffffu

static __device__ __forceinline__ float fixv(float p) {
    return (p == -1.0f) ? 0.0f : p;
}

static __device__ __forceinline__ float tanh_fast(float x) {
    float y;
    asm("tanh.approx.f32 %0, %1;" : "=f"(y) : "f"(x));
    return y;
}

// One CTA per batch image, 512 threads, 2 cols x 4 rows per thread.
// Warp w (of 16) owns image rows 4w..4w+3; lane j owns cols 2j,2j+1.
//
// Separable stencil with register-resident interior: per iteration each
// thread builds horizontal 3-sums h0..h3 for its 4 rows (8 shuffles), stores
// only the BOUNDARY rows h0,h3 to smem (interior h1,h2 never leave
// registers), computes the interior outputs u1,u2 BEFORE the barrier (they
// depend only on own h-rows — this MUFU work hides the barrier), then after
// __syncthreads loads the 2 halo h-rows and finishes u0,u3.
__global__ __launch_bounds__(512, 1)
void prop_kernel(const float* __restrict__ X,
                 const float* __restrict__ pred,
                 const float* __restrict__ w,
                 const float* __restrict__ a,
                 const float* __restrict__ bias,
                 const float* __restrict__ scalar,
                 float* __restrict__ out)
{
    constexpr int NS = 64;          // image side
    constexpr int HH = NS * NS;     // 4096 pixels
    constexpr int SROWS = 66;       // +1 zero halo row each side (idx = row+1)
    constexpr int ITERS = 12;

    __shared__ float Hs[2][SROWS * NS];   // boundary h-rows, double buffered

    const int b    = blockIdx.x;
    const int t    = threadIdx.x;
    const int wrp  = t >> 5;        // 0..15 -> rows 4w..4w+3
    const int lane = t & 31;        // cols 2j, 2j+1

    // Zero halo rows (halo idx 0 and 65) in both buffers, once.
    if (t < NS) {
        Hs[0][t] = 0.f;            Hs[1][t] = 0.f;
        Hs[0][65 * NS + t] = 0.f;  Hs[1][65 * NS + t] = 0.f;
    }

    const float s  = scalar[0];
    const int r0 = wrp * 4;             // first owned row
    const int c  = lane * 2;            // left col
    const int g0 = b * HH + r0 * NS + c;
    const int p0 = r0 * NS + c;

    // ---- per-row parameter setup: cs = s*(u_fix+bias+a*X), sw = s*w ----
    float2 u0, u1, u2, u3;              // state, one float2 per row
    float2 cs0, cs1, cs2, cs3, sw0, sw1, sw2, sw3;
    {
        float2 pr, xx, ww, aa, bb;
        #define SETUP(K)                                                     \
            pr = *(const float2*)(pred + g0 + (K) * NS);                     \
            xx = *(const float2*)(X    + g0 + (K) * NS);                     \
            ww = *(const float2*)(w    + p0 + (K) * NS);                     \
            aa = *(const float2*)(a    + p0 + (K) * NS);                     \
            bb = *(const float2*)(bias + p0 + (K) * NS);                     \
            cs##K.x = s * (fixv(pr.x) + bb.x + aa.x * xx.x);                 \
            cs##K.y = s * (fixv(pr.y) + bb.y + aa.y * xx.y);                 \
            sw##K.x = s * ww.x;  sw##K.y = s * ww.y;                         \
            u##K = pr;
        SETUP(0) SETUP(1) SETUP(2) SETUP(3)
        #undef SETUP
    }

    // smem indices (image row r -> halo idx r+1)
    const int stT = (r0 + 1) * NS + c;   // own top boundary h-row (row 4w)
    const int stB = (r0 + 4) * NS + c;   // own bottom boundary h-row (row 4w+3)
    const int ldU =  r0      * NS + c;   // halo above (row 4w-1)
    const int ldD = (r0 + 5) * NS + c;   // halo below (row 4w+4)

    __syncthreads();

    #pragma unroll
    for (int it = 0; it < ITERS; ++it) {
        float* __restrict__ Hc = Hs[it & 1];

        // ---- horizontal 3-sums for all 4 owned rows (8 shuffles) ----
        float2 h0, h1, h2, h3;
        {
            float s0 = u0.x + u0.y, s1 = u1.x + u1.y;
            float s2 = u2.x + u2.y, s3 = u3.x + u3.y;
            float l0 = __shfl_up_sync  (FULLMASK, u0.y, 1);
            float r0s= __shfl_down_sync(FULLMASK, u0.x, 1);
            float l1 = __shfl_up_sync  (FULLMASK, u1.y, 1);
            float r1s= __shfl_down_sync(FULLMASK, u1.x, 1);
            float l2 = __shfl_up_sync  (FULLMASK, u2.y, 1);
            float r2s= __shfl_down_sync(FULLMASK, u2.x, 1);
            float l3 = __shfl_up_sync  (FULLMASK, u3.y, 1);
            float r3s= __shfl_down_sync(FULLMASK, u3.x, 1);
            if (lane == 0)  { l0 = 0.f; l1 = 0.f; l2 = 0.f; l3 = 0.f; }
            if (lane == 31) { r0s = 0.f; r1s = 0.f; r2s = 0.f; r3s = 0.f; }
            h0 = make_float2(l0 + s0, s0 + r0s);
            h1 = make_float2(l1 + s1, s1 + r1s);
            h2 = make_float2(l2 + s2, s2 + r2s);
            h3 = make_float2(l3 + s3, s3 + r3s);
        }

        // ---- publish boundary rows only ----
        *(float2*)&Hc[stT] = h0;
        *(float2*)&Hc[stB] = h3;

        // ---- interior outputs need no smem: compute BEFORE the barrier ----
        float2 v1 = make_float2(h0.x + h1.x + h2.x, h0.y + h1.y + h2.y);
        float2 v2 = make_float2(h1.x + h2.x + h3.x, h1.y + h2.y + h3.y);
        u1.x = tanh_fast(fmaf(sw1.x, v1.x, cs1.x));
        u1.y = tanh_fast(fmaf(sw1.y, v1.y, cs1.y));
        u2.x = tanh_fast(fmaf(sw2.x, v2.x, cs2.x));
        u2.y = tanh_fast(fmaf(sw2.y, v2.y, cs2.y));

        // partial boundary sums (register part)
        float2 t0 = make_float2(h0.x + h1.x, h0.y + h1.y);
        float2 t3 = make_float2(h2.x + h3.x, h2.y + h3.y);

        __syncthreads();

        // ---- halo h-rows, finish boundary outputs ----
        const float2 hU = *(const float2*)&Hc[ldU];
        const float2 hD = *(const float2*)&Hc[ldD];

        u0.x = tanh_fast(fmaf(sw0.x, hU.x + t0.x, cs0.x));
        u0.y = tanh_fast(fmaf(sw0.y, hU.y + t0.y, cs0.y));
        u3.x = tanh_fast(fmaf(sw3.x, t3.x + hD.x, cs3.x));
        u3.y = tanh_fast(fmaf(sw3.y, t3.y + hD.y, cs3.y));
    }

    *(float2*)(out + g0)          = u0;
    *(float2*)(out + g0 + NS)     = u1;
    *(float2*)(out + g0 + 2 * NS) = u2;
    *(float2*)(out + g0 + 3 * NS) = u3;
}

extern "C" void kernel_launch(void* const* d_in, const int* in_sizes, int n_in,
                              void* d_out, int out_size) {
    const float* X      = (const float*)d_in[0];
    const float* pred   = (const float*)d_in[1];
    const float* w      = (const float*)d_in[2];
    const float* a      = (const float*)d_in[3];
    const float* bias   = (const float*)d_in[4];
    const float* scalar = (const float*)d_in[5];
    float* out = (float*)d_out;

    const int B = in_sizes[0] / 4096;   // batch = 128
    prop_kernel<<<B, 512>>>(X, pred, w, a, bias, scalar, out);
}